// round 4
// baseline (speedup 1.0000x reference)
#include <cuda_runtime.h>
#include <cstdint>

typedef unsigned long long u64;

// ---- packed f32x2 helpers ----
__device__ __forceinline__ u64 ffma2(u64 a, u64 b, u64 c) {
    u64 d;
    asm("fma.rn.f32x2 %0, %1, %2, %3;" : "=l"(d) : "l"(a), "l"(b), "l"(c));
    return d;
}
__device__ __forceinline__ u64 addf2(u64 a, u64 b) {
    u64 d;
    asm("add.rn.f32x2 %0, %1, %2;" : "=l"(d) : "l"(a), "l"(b));
    return d;
}
__device__ __forceinline__ u64 pk(float x, float y) {
    u64 r; asm("mov.b64 %0, {%1, %2};" : "=l"(r) : "f"(x), "f"(y)); return r;
}
__device__ __forceinline__ float2 unpk(u64 v) {
    float2 r;
    asm("mov.b64 {%0, %1}, %2;" : "=f"(r.x), "=f"(r.y) : "l"(v));
    return r;
}

#define KD 25088
#define KH 4096
#define NROI 2048
#define NOUT 25
#define NCLS_ 21
#define HSPLIT 8
#define HPER (KH / HSPLIT)    // 512
#define KSEG 512
#define NSEG (KD / KSEG)      // 49
#define NRG 32                // 2048/64 rowgroups
#define PIT 68

// scratch (static device arrays)
__device__ __align__(16) float g_part[(size_t)HSPLIT * NOUT * KD];   // 20 MB
__device__ __align__(16) float g_M[NOUT * KD];                       // 2.5 MB
__device__ __align__(16) float g_p2[(size_t)NSEG * NRG * NOUT * 64]; // 10 MB
__device__ float g_biasf[NOUT];
__device__ float g_score[NROI];
__device__ __align__(16) float g_boxes[NROI * 4];

// ---------------- fused bias ----------------
__global__ void k_bias(const float* __restrict__ b1, const float* __restrict__ Wc,
                       const float* __restrict__ bc, const float* __restrict__ Wr,
                       const float* __restrict__ br) {
    int c = blockIdx.x;
    int tid = threadIdx.x;
    const float* p = (c < NCLS_) ? (Wc + (size_t)c * KH) : (Wr + (size_t)(c - NCLS_) * KH);
    float s = 0.f;
    for (int h = tid; h < KH; h += 256) s += b1[h] * p[h];
    __shared__ float red[256];
    red[tid] = s;
    __syncthreads();
    for (int o = 128; o > 0; o >>= 1) {
        if (tid < o) red[tid] += red[tid + o];
        __syncthreads();
    }
    if (tid == 0) g_biasf[c] = red[0] + ((c < NCLS_) ? bc[c] : br[c - NCLS_]);
}

// ---------------- k1: partial M[c,d] = sum_h P[c,h]*W1[h,d] ----------------
// 256 thr, thread owns ONE d-pair (2 d) -> acc[25] u64 (50 regs). 24 warps/SM.
// P staged per 128-h chunk as dup pairs; one LDS.128 gives (P[h],P[h]),(P[h+1],P[h+1]).
// W rows prefetched one j2 (~2 rounds of 50 FFMA2 x 6 warps) ahead.
__global__ __launch_bounds__(256, 3) void k1_partial(const float* __restrict__ W1,
                                                     const float* __restrict__ Wc,
                                                     const float* __restrict__ Wr) {
    __shared__ __align__(16) u64 sPd[64][NOUT][2];   // 25.6 KB
    int tid = threadIdx.x;
    int d = blockIdx.x * 512 + tid * 2;
    int hbase = blockIdx.y * HPER;

    u64 acc[NOUT];
#pragma unroll
    for (int c = 0; c < NOUT; c++) acc[c] = 0ull;

    for (int ch = 0; ch < HPER / 128; ch++) {        // 4 chunks of 128 h
        int h0 = hbase + ch * 128;
        __syncthreads();
        for (int i = tid; i < 64 * NOUT; i += 256) {
            int j2 = i & 63, c = i >> 6;
            int h = h0 + 2 * j2;
            float v0, v1;
            if (c < NCLS_) { v0 = Wc[(size_t)c * KH + h]; v1 = Wc[(size_t)c * KH + h + 1]; }
            else { v0 = Wr[(size_t)(c - NCLS_) * KH + h]; v1 = Wr[(size_t)(c - NCLS_) * KH + h + 1]; }
            sPd[j2][c][0] = pk(v0, v0);
            sPd[j2][c][1] = pk(v1, v1);
        }
        __syncthreads();

        u64 w0 = *reinterpret_cast<const u64*>(W1 + (size_t)h0 * KD + d);
        u64 w1 = *reinterpret_cast<const u64*>(W1 + (size_t)(h0 + 1) * KD + d);
#pragma unroll 2
        for (int j2 = 0; j2 < 64; j2++) {
            // prefetch next h-pair (next chunk's first pair at j2==63)
            int hn = (j2 < 63) ? (h0 + 2 * (j2 + 1)) : ((ch < 3) ? h0 + 128 : hbase);
            u64 nw0 = *reinterpret_cast<const u64*>(W1 + (size_t)hn * KD + d);
            u64 nw1 = *reinterpret_cast<const u64*>(W1 + (size_t)(hn + 1) * KD + d);
#pragma unroll
            for (int c = 0; c < NOUT; c++) {
                ulonglong2 m = *reinterpret_cast<const ulonglong2*>(&sPd[j2][c][0]);
                acc[c] = ffma2(m.x, w0, acc[c]);
                acc[c] = ffma2(m.y, w1, acc[c]);
            }
            w0 = nw0; w1 = nw1;
        }
    }
    float* op = g_part + (size_t)blockIdx.y * NOUT * KD + d;
#pragma unroll
    for (int c = 0; c < NOUT; c++)
        *reinterpret_cast<u64*>(op + (size_t)c * KD) = acc[c];
}

// ---------------- reduce partials -> M ----------------
__global__ void k_reduce() {
    int i = blockIdx.x * 256 + threadIdx.x;   // < 313600 u64
    const u64* gp = reinterpret_cast<const u64*>(g_part);
    u64 s = gp[i];
#pragma unroll
    for (int p = 1; p < HSPLIT; p++) s = addf2(s, gp[(size_t)p * 313600 + i]);
    reinterpret_cast<u64*>(g_M)[i] = s;
}

// ---------------- k2_main: logits partials, k-major register GEMM ----------------
// grid (NRG, NSEG), 256 thr = 8 warps: q=w>>1 k-quarter, half=w&1 row-half.
// Thread owns ONE row -> acc[25] u64. Double-buffered shared + LDG prefetch.
__global__ __launch_bounds__(256, 3) void k2_main(const float* __restrict__ feats) {
    __shared__ __align__(16) float sF[2][64 * PIT];   // 34.8 KB
    __shared__ __align__(16) float sM[2][NOUT * PIT]; // 13.6 KB
    int tid = threadIdx.x, w = tid >> 5, lane = tid & 31;
    int q = w >> 1, half = w & 1;
    int rg = blockIdx.x, ks = blockIdx.y;
    int rowbase = rg * 64;
    int kbase = ks * KSEG;
    int row_local = half * 32 + lane;

    u64 acc[NOUT];
#pragma unroll
    for (int c = 0; c < NOUT; c++) acc[c] = 0ull;

    int fk4 = (tid & 15) * 4;        // float4 k-offset
    int fr0 = tid >> 4;              // base staging row (stride 16)

    float4 fb[4]; float4 mb[2];
    // prologue: chunk 0
    {
        int k0 = kbase;
#pragma unroll
        for (int qq = 0; qq < 4; qq++)
            fb[qq] = *reinterpret_cast<const float4*>(feats + (size_t)(rowbase + fr0 + 16 * qq) * KD + k0 + fk4);
#pragma unroll
        for (int j = 0; j < 2; j++) {
            int idx = tid + 256 * j;
            if (idx < NOUT * 16)
                mb[j] = *reinterpret_cast<const float4*>(g_M + (size_t)(idx >> 4) * KD + k0 + (idx & 15) * 4);
        }
#pragma unroll
        for (int qq = 0; qq < 4; qq++)
            *reinterpret_cast<float4*>(&sF[0][(fr0 + 16 * qq) * PIT + fk4]) = fb[qq];
#pragma unroll
        for (int j = 0; j < 2; j++) {
            int idx = tid + 256 * j;
            if (idx < NOUT * 16)
                *reinterpret_cast<float4*>(&sM[0][(idx >> 4) * PIT + (idx & 15) * 4]) = mb[j];
        }
    }
    __syncthreads();

    for (int ch = 0; ch < 8; ch++) {
        int b = ch & 1;
        bool pf = (ch < 7);
        if (pf) {
            int k0 = kbase + (ch + 1) * 64;
#pragma unroll
            for (int qq = 0; qq < 4; qq++)
                fb[qq] = *reinterpret_cast<const float4*>(feats + (size_t)(rowbase + fr0 + 16 * qq) * KD + k0 + fk4);
#pragma unroll
            for (int j = 0; j < 2; j++) {
                int idx = tid + 256 * j;
                if (idx < NOUT * 16)
                    mb[j] = *reinterpret_cast<const float4*>(g_M + (size_t)(idx >> 4) * KD + k0 + (idx & 15) * 4);
            }
        }
        const float* F = sF[b];
        const float* M = sM[b];
#pragma unroll
        for (int kk = 0; kk < 16; kk += 4) {
            int k = q * 16 + kk;
            ulonglong2 f = *reinterpret_cast<const ulonglong2*>(F + row_local * PIT + k);
#pragma unroll
            for (int c = 0; c < NOUT; c++) {
                ulonglong2 m = *reinterpret_cast<const ulonglong2*>(M + c * PIT + k);
                acc[c] = ffma2(f.x, m.x, acc[c]);
                acc[c] = ffma2(f.y, m.y, acc[c]);
            }
        }
        if (pf) {
            int nb = 1 - b;
#pragma unroll
            for (int qq = 0; qq < 4; qq++)
                *reinterpret_cast<float4*>(&sF[nb][(fr0 + 16 * qq) * PIT + fk4]) = fb[qq];
#pragma unroll
            for (int j = 0; j < 2; j++) {
                int idx = tid + 256 * j;
                if (idx < NOUT * 16)
                    *reinterpret_cast<float4*>(&sM[nb][(idx >> 4) * PIT + (idx & 15) * 4]) = mb[j];
            }
            __syncthreads();
        }
    }

    // k-quarter reduction: q0/q1 store A/B, q2/q3 add, then combine.
    __syncthreads();
    u64* SA = reinterpret_cast<u64*>(&sF[0][0]);     // 1600 u64
    u64* SB = SA + 1600;
    int base = half * 800 + lane;
    if (q == 0) {
#pragma unroll
        for (int c = 0; c < NOUT; c++) SA[base + c * 32] = acc[c];
    } else if (q == 1) {
#pragma unroll
        for (int c = 0; c < NOUT; c++) SB[base + c * 32] = acc[c];
    }
    __syncthreads();
    if (q == 2) {
#pragma unroll
        for (int c = 0; c < NOUT; c++) SA[base + c * 32] = addf2(SA[base + c * 32], acc[c]);
    } else if (q == 3) {
#pragma unroll
        for (int c = 0; c < NOUT; c++) SB[base + c * 32] = addf2(SB[base + c * 32], acc[c]);
    }
    __syncthreads();
    float* outp = g_p2 + (size_t)(ks * NRG + rg) * (NOUT * 64);
    for (int i = tid; i < 1600; i += 256) {
        int hf = i / 800, rem = i - hf * 800;
        int c = rem >> 5, ln = rem & 31;
        float2 v = unpk(addf2(SA[i], SB[i]));
        outp[c * 64 + hf * 32 + ln] = v.x + v.y;
    }
}

// ---------------- k2r: sum seg partials + softmax/argmax/box decode ----------------
__global__ __launch_bounds__(256) void k2r(const float* __restrict__ props) {
    int tid = threadIdx.x, lane = tid & 31;
    int row = blockIdx.x * 8 + (tid >> 5);
    int rg = row >> 6, rowin = row & 63;

    float t[NOUT];
#pragma unroll
    for (int c = 0; c < NOUT; c++) t[c] = 0.f;
#pragma unroll
    for (int half = 0; half < 2; half++) {
        int s = lane + half * 32;
        if (s < NSEG) {
            const float* base = g_p2 + (size_t)(s * NRG + rg) * (NOUT * 64) + rowin;
#pragma unroll
            for (int c = 0; c < NOUT; c++) t[c] += base[c * 64];
        }
    }
#pragma unroll
    for (int c = 0; c < NOUT; c++) {
#pragma unroll
        for (int o = 16; o > 0; o >>= 1) t[c] += __shfl_xor_sync(0xffffffffu, t[c], o);
    }

    if (lane == 0) {
#pragma unroll
        for (int c = 0; c < NOUT; c++) t[c] += g_biasf[c];
        float m = t[0]; int idx = 0;
#pragma unroll
        for (int c = 1; c < NCLS_; c++) { if (t[c] > m) { m = t[c]; idx = c; } }
        float ssum = 0.f;
#pragma unroll
        for (int c = 0; c < NCLS_; c++) ssum += expf(t[c] - m);
        float score = 1.f / ssum;
        bool valid = (idx != 0) && (score >= 0.01f);
        float p0 = props[row * 4 + 0], p1 = props[row * 4 + 1];
        float p2 = props[row * 4 + 2], p3 = props[row * 4 + 3];
        g_score[row] = valid ? score : 0.f;
        g_boxes[row * 4 + 0] = p0 + p2 * t[NCLS_ + 0];
        g_boxes[row * 4 + 1] = p1 + p3 * t[NCLS_ + 1];
        g_boxes[row * 4 + 2] = p2 * expf(t[NCLS_ + 2]);
        g_boxes[row * 4 + 3] = p3 * expf(t[NCLS_ + 3]);
    }
}

// ---------------- k3: exact greedy NMS per batch ----------------
__global__ __launch_bounds__(512) void k3_nms(float* __restrict__ out) {
    __shared__ float sraw[512];
    __shared__ float ss[512], sx0[512], sy0[512], sx1[512], sy1[512], sa[512];
    __shared__ short sord[512];
    __shared__ unsigned char ssup[512];

    int b = blockIdx.x, t = threadIdx.x;
    int gi = b * 512 + t;
    float sc = g_score[gi];
    sraw[t] = sc;
    float bx = g_boxes[gi * 4 + 0], by = g_boxes[gi * 4 + 1];
    float bw = g_boxes[gi * 4 + 2], bh = g_boxes[gi * 4 + 3];
    __syncthreads();

    int r = 0;
    for (int i = 0; i < 512; i++) {
        float si = sraw[i];
        r += (si > sc) || (si == sc && i < t);
    }

    float x0 = fminf(fmaxf(bx, 0.f), 599.f);
    float y0 = fminf(fmaxf(by, 0.f), 599.f);
    float x1 = fminf(fmaxf(bx + bw - 1.f, 0.f), 599.f);
    float y1 = fminf(fmaxf(by + bh - 1.f, 0.f), 599.f);
    float area = fmaxf(x1 - x0 + 1.f, 0.f) * fmaxf(y1 - y0 + 1.f, 0.f);

    ss[r] = sc; sx0[r] = x0; sy0[r] = y0; sx1[r] = x1; sy1[r] = y1; sa[r] = area;
    sord[r] = (short)t;
    ssup[t] = 0;
    __syncthreads();

    for (int i = 0; i < 512; i++) {
        bool alive = (!ssup[i]) && (ss[i] > 0.f);
        if (alive && t != i) {
            float ix0 = fmaxf(sx0[i], sx0[t]);
            float iy0 = fmaxf(sy0[i], sy0[t]);
            float ix1 = fminf(sx1[i], sx1[t]);
            float iy1 = fminf(sy1[i], sy1[t]);
            float inter = fmaxf(ix1 - ix0 + 1.f, 0.f) * fmaxf(iy1 - iy0 + 1.f, 0.f);
            float iou = inter / (sa[i] + sa[t] - inter + 1e-9f);
            if (iou > 0.5f) ssup[t] = 1;
        }
        __syncthreads();
    }

    bool keep = (!ssup[t]) && (ss[t] > 0.f);
    int orig = sord[t];
    int go = b * 512 + orig;

    out[go] = keep ? ss[t] : 0.f;

    float obx = g_boxes[go * 4 + 0], oby = g_boxes[go * 4 + 1];
    float obw = g_boxes[go * 4 + 2], obh = g_boxes[go * 4 + 3];
    float* ob = out + NROI + (size_t)go * 4;
    if (keep) {
        ob[0] = obx; ob[1] = oby;
        ob[2] = obx + obw - 1.f;
        ob[3] = oby + obh - 1.f;
    } else {
        ob[0] = 0.f; ob[1] = 0.f; ob[2] = -1.f; ob[3] = -1.f;
    }
}

extern "C" void kernel_launch(void* const* d_in, const int* in_sizes, int n_in,
                              void* d_out, int out_size) {
    (void)in_sizes; (void)n_in; (void)out_size;
    const float* rois  = (const float*)d_in[0];
    const float* props = (const float*)d_in[1];
    const float* W1    = (const float*)d_in[2];
    const float* b1    = (const float*)d_in[3];
    const float* Wc    = (const float*)d_in[4];
    const float* bc    = (const float*)d_in[5];
    const float* Wr    = (const float*)d_in[6];
    const float* br    = (const float*)d_in[7];
    float* out = (float*)d_out;

    k_bias<<<NOUT, 256>>>(b1, Wc, bc, Wr, br);
    dim3 g1(KD / 512, HSPLIT);                 // (49, 8)
    k1_partial<<<g1, 256>>>(W1, Wc, Wr);
    k_reduce<<<313600 / 256, 256>>>();
    dim3 g2(NRG, NSEG);                        // (32, 49)
    k2_main<<<g2, 256>>>(rois);
    k2r<<<NROI / 8, 256>>>(props);
    k3_nms<<<4, 512>>>(out);
}

// round 5
// speedup vs baseline: 1.2711x; 1.2711x over previous
#include <cuda_runtime.h>
#include <cstdint>

typedef unsigned long long u64;

// ---- packed f32x2 helpers ----
__device__ __forceinline__ u64 ffma2(u64 a, u64 b, u64 c) {
    u64 d;
    asm("fma.rn.f32x2 %0, %1, %2, %3;" : "=l"(d) : "l"(a), "l"(b), "l"(c));
    return d;
}
__device__ __forceinline__ u64 addf2(u64 a, u64 b) {
    u64 d;
    asm("add.rn.f32x2 %0, %1, %2;" : "=l"(d) : "l"(a), "l"(b));
    return d;
}
__device__ __forceinline__ u64 pk(float x, float y) {
    u64 r; asm("mov.b64 %0, {%1, %2};" : "=l"(r) : "f"(x), "f"(y)); return r;
}
__device__ __forceinline__ float2 unpk(u64 v) {
    float2 r;
    asm("mov.b64 {%0, %1}, %2;" : "=f"(r.x), "=f"(r.y) : "l"(v));
    return r;
}

#define KD 25088
#define KH 4096
#define NROI 2048
#define NOUT 25
#define NCLS_ 21
#define HSPLIT 8
#define HPER (KH / HSPLIT)    // 512
#define KSEG 512
#define NSEG (KD / KSEG)      // 49
#define NRG 32                // 2048/64 rowgroups

// scratch (static device arrays)
__device__ __align__(16) float g_part[(size_t)HSPLIT * NOUT * KD];   // 20 MB
__device__ __align__(16) float g_M[NOUT * KD];                       // 2.5 MB
__device__ __align__(16) float g_p2[(size_t)NSEG * NRG * NOUT * 64]; // 10 MB
__device__ float g_biasf[NOUT];
__device__ float g_score[NROI];
__device__ __align__(16) float g_boxes[NROI * 4];

// ---------------- fused bias ----------------
__global__ void k_bias(const float* __restrict__ b1, const float* __restrict__ Wc,
                       const float* __restrict__ bc, const float* __restrict__ Wr,
                       const float* __restrict__ br) {
    int c = blockIdx.x;
    int tid = threadIdx.x;
    const float* p = (c < NCLS_) ? (Wc + (size_t)c * KH) : (Wr + (size_t)(c - NCLS_) * KH);
    float s = 0.f;
    for (int h = tid; h < KH; h += 256) s += b1[h] * p[h];
    __shared__ float red[256];
    red[tid] = s;
    __syncthreads();
    for (int o = 128; o > 0; o >>= 1) {
        if (tid < o) red[tid] += red[tid + o];
        __syncthreads();
    }
    if (tid == 0) g_biasf[c] = red[0] + ((c < NCLS_) ? bc[c] : br[c - NCLS_]);
}

// ---------------- k1: partial M[c,d] = sum_h P[c,h]*W1[h,d] ----------------
// 128 thr, T=2: thread owns 4 consecutive d (2 f32x2 pairs). acc[25][2] = 100 regs.
// P staged per 128-h chunk as duplicated pairs; 1 broadcast LDS.128 per (c, h-pair).
// W rows loaded in groups of 4 h (4 x LDG.128), prefetched one group ahead.
__global__ __launch_bounds__(128, 3) void k1_partial(const float* __restrict__ W1,
                                                     const float* __restrict__ Wc,
                                                     const float* __restrict__ Wr) {
    __shared__ __align__(16) u64 sPd[64][NOUT][2];   // 25.6 KB: [h-pair][c][h-parity]
    int tid = threadIdx.x;
    int d = blockIdx.x * 512 + tid * 4;
    int hbase = blockIdx.y * HPER;

    u64 acc[NOUT][2];
#pragma unroll
    for (int c = 0; c < NOUT; c++) { acc[c][0] = 0ull; acc[c][1] = 0ull; }

    for (int ch = 0; ch < HPER / 128; ch++) {        // 4 chunks of 128 h
        int h0 = hbase + ch * 128;
        __syncthreads();
        for (int i = tid; i < 64 * NOUT; i += 128) {
            int c = i >> 6, j2 = i & 63;
            int h = h0 + 2 * j2;
            float v0, v1;
            if (c < NCLS_) { v0 = Wc[(size_t)c * KH + h]; v1 = Wc[(size_t)c * KH + h + 1]; }
            else { v0 = Wr[(size_t)(c - NCLS_) * KH + h]; v1 = Wr[(size_t)(c - NCLS_) * KH + h + 1]; }
            sPd[j2][c][0] = pk(v0, v0);
            sPd[j2][c][1] = pk(v1, v1);
        }
        __syncthreads();

        float4 cur[4], nxt[4];
#pragma unroll
        for (int q = 0; q < 4; q++)
            cur[q] = *reinterpret_cast<const float4*>(W1 + (size_t)(h0 + q) * KD + d);

        for (int g = 0; g < 32; g++) {               // group = 4 h
            if (g < 31) {
#pragma unroll
                for (int q = 0; q < 4; q++)
                    nxt[q] = *reinterpret_cast<const float4*>(W1 + (size_t)(h0 + 4 * (g + 1) + q) * KD + d);
            }
            int j2a = 2 * g, j2b = 2 * g + 1;
#pragma unroll
            for (int c = 0; c < NOUT; c++) {
                ulonglong2 ma = *reinterpret_cast<const ulonglong2*>(&sPd[j2a][c][0]);
                ulonglong2 mb = *reinterpret_cast<const ulonglong2*>(&sPd[j2b][c][0]);
                const u64* w0 = reinterpret_cast<const u64*>(&cur[0]);
                const u64* w1 = reinterpret_cast<const u64*>(&cur[1]);
                const u64* w2 = reinterpret_cast<const u64*>(&cur[2]);
                const u64* w3 = reinterpret_cast<const u64*>(&cur[3]);
                acc[c][0] = ffma2(ma.x, w0[0], acc[c][0]);
                acc[c][1] = ffma2(ma.x, w0[1], acc[c][1]);
                acc[c][0] = ffma2(ma.y, w1[0], acc[c][0]);
                acc[c][1] = ffma2(ma.y, w1[1], acc[c][1]);
                acc[c][0] = ffma2(mb.x, w2[0], acc[c][0]);
                acc[c][1] = ffma2(mb.x, w2[1], acc[c][1]);
                acc[c][0] = ffma2(mb.y, w3[0], acc[c][0]);
                acc[c][1] = ffma2(mb.y, w3[1], acc[c][1]);
            }
#pragma unroll
            for (int q = 0; q < 4; q++) cur[q] = nxt[q];
        }
    }
    float* op = g_part + (size_t)blockIdx.y * NOUT * KD + d;
#pragma unroll
    for (int c = 0; c < NOUT; c++) {
        ulonglong2 v; v.x = acc[c][0]; v.y = acc[c][1];
        *reinterpret_cast<ulonglong2*>(op + (size_t)c * KD) = v;
    }
}

// ---------------- reduce partials -> M ----------------
__global__ void k_reduce() {
    int i = blockIdx.x * 256 + threadIdx.x;   // < 313600 u64
    const u64* gp = reinterpret_cast<const u64*>(g_part);
    u64 s = gp[i];
#pragma unroll
    for (int p = 1; p < HSPLIT; p++) s = addf2(s, gp[(size_t)p * 313600 + i]);
    reinterpret_cast<u64*>(g_M)[i] = s;
}

// ---------------- k2_main: logits partials, k-major tile with XOR swizzle ----------------
// grid (NRG, NSEG), 128 thr = 4 warps; warp w owns kp-quarter of each 128-k chunk.
// Thread owns rows (2*lane, 2*lane+1): acc[25][2] (k-pair partials).
// sFk[kp][slot] u64, slot = row ^ ((2*kp)&63): compute LDS.128 coalesced (4 phases),
// staging STS.64 <=4-way. sM[c][kp] broadcast (1 phase).
#define K2SFK (64 * 64)          // u64 entries (128 k x 64 rows)
#define K2SM  (NOUT * 64)        // u64 entries
__global__ __launch_bounds__(128, 3) void k2_main(const float* __restrict__ feats) {
    __shared__ __align__(16) unsigned char smem_raw[(K2SFK + K2SM) * 8];  // 45.3 KB
    u64 (*sFk)[64] = reinterpret_cast<u64(*)[64]>(smem_raw);
    u64 (*sM)[64] = reinterpret_cast<u64(*)[64]>(smem_raw + K2SFK * 8);
    float* sRed = reinterpret_cast<float*>(smem_raw);    // aliased after compute

    int tid = threadIdx.x, w = tid >> 5, lane = tid & 31;
    int rg = blockIdx.x, ks = blockIdx.y;
    int rowbase = rg * 64;
    int kbase = ks * KSEG;
    int srow = tid >> 4;        // staging: base row 0..7
    int skl = tid & 15;         // staging: k-lane

    u64 acc[NOUT][2];
#pragma unroll
    for (int c = 0; c < NOUT; c++) { acc[c][0] = 0ull; acc[c][1] = 0ull; }

    for (int chunk = 0; chunk < 4; chunk++) {            // 4 x 128 k
        int k0 = kbase + chunk * 128;
        __syncthreads();
        // stage feats: 16 (row, kq) units per thread, batched 8 for MLP
#pragma unroll
        for (int half = 0; half < 2; half++) {
            float4 fv[8];
#pragma unroll
            for (int p = 0; p < 8; p++) {
                int pass = half * 8 + p;
                int row = srow + 8 * (pass & 7);
                int kq = skl + 16 * (pass >> 3);
                fv[p] = *reinterpret_cast<const float4*>(feats + (size_t)(rowbase + row) * KD + k0 + kq * 4);
            }
#pragma unroll
            for (int p = 0; p < 8; p++) {
                int pass = half * 8 + p;
                int row = srow + 8 * (pass & 7);
                int kq = skl + 16 * (pass >> 3);
                int kp = kq * 2;
                sFk[kp][row ^ ((2 * kp) & 63)]     = pk(fv[p].x, fv[p].y);
                sFk[kp + 1][row ^ ((2 * kp + 2) & 63)] = pk(fv[p].z, fv[p].w);
            }
        }
        // stage M: 800 float4 -> 25 x 64 u64
        for (int i = tid; i < NOUT * 32; i += 128) {
            int c = i >> 5, kq = i & 31;
            float4 mv = *reinterpret_cast<const float4*>(g_M + (size_t)c * KD + k0 + kq * 4);
            ulonglong2 e; e.x = pk(mv.x, mv.y); e.y = pk(mv.z, mv.w);
            *reinterpret_cast<ulonglong2*>(&sM[c][kq * 2]) = e;
        }
        __syncthreads();
        // compute: warp's 16 kp, 2 per step
#pragma unroll
        for (int kk = 0; kk < 16; kk += 2) {
            int kp = w * 16 + kk;
            ulonglong2 f0 = *reinterpret_cast<const ulonglong2*>(&sFk[kp][(2 * lane) ^ ((2 * kp) & 63)]);
            ulonglong2 f1 = *reinterpret_cast<const ulonglong2*>(&sFk[kp + 1][(2 * lane) ^ ((2 * kp + 2) & 63)]);
#pragma unroll
            for (int c = 0; c < NOUT; c++) {
                ulonglong2 m = *reinterpret_cast<const ulonglong2*>(&sM[c][kp]);
                acc[c][0] = ffma2(f0.x, m.x, acc[c][0]);
                acc[c][1] = ffma2(f0.y, m.x, acc[c][1]);
                acc[c][0] = ffma2(f1.x, m.y, acc[c][0]);
                acc[c][1] = ffma2(f1.y, m.y, acc[c][1]);
            }
        }
    }

    // cross-warp reduce via shared (aliases sFk; safe after sync)
    __syncthreads();
#pragma unroll
    for (int c = 0; c < NOUT; c++) {
        float2 a = unpk(acc[c][0]);
        float2 b = unpk(acc[c][1]);
        sRed[w * 1600 + c * 64 + 2 * lane]     = a.x + a.y;
        sRed[w * 1600 + c * 64 + 2 * lane + 1] = b.x + b.y;
    }
    __syncthreads();
    float* outp = g_p2 + (size_t)(ks * NRG + rg) * (NOUT * 64);
    for (int i = tid; i < 1600; i += 128) {
        float v = sRed[i] + sRed[1600 + i] + sRed[3200 + i] + sRed[4800 + i];
        outp[i] = v;
    }
}

// ---------------- k2r: sum seg partials + softmax/argmax/box decode ----------------
__global__ __launch_bounds__(256) void k2r(const float* __restrict__ props) {
    int tid = threadIdx.x, lane = tid & 31;
    int row = blockIdx.x * 8 + (tid >> 5);
    int rg = row >> 6, rowin = row & 63;

    float t[NOUT];
#pragma unroll
    for (int c = 0; c < NOUT; c++) t[c] = 0.f;
#pragma unroll
    for (int half = 0; half < 2; half++) {
        int s = lane + half * 32;
        if (s < NSEG) {
            const float* base = g_p2 + (size_t)(s * NRG + rg) * (NOUT * 64) + rowin;
#pragma unroll
            for (int c = 0; c < NOUT; c++) t[c] += base[c * 64];
        }
    }
#pragma unroll
    for (int c = 0; c < NOUT; c++) {
#pragma unroll
        for (int o = 16; o > 0; o >>= 1) t[c] += __shfl_xor_sync(0xffffffffu, t[c], o);
    }

    if (lane == 0) {
#pragma unroll
        for (int c = 0; c < NOUT; c++) t[c] += g_biasf[c];
        float m = t[0]; int idx = 0;
#pragma unroll
        for (int c = 1; c < NCLS_; c++) { if (t[c] > m) { m = t[c]; idx = c; } }
        float ssum = 0.f;
#pragma unroll
        for (int c = 0; c < NCLS_; c++) ssum += expf(t[c] - m);
        float score = 1.f / ssum;
        bool valid = (idx != 0) && (score >= 0.01f);
        float p0 = props[row * 4 + 0], p1 = props[row * 4 + 1];
        float p2 = props[row * 4 + 2], p3 = props[row * 4 + 3];
        g_score[row] = valid ? score : 0.f;
        g_boxes[row * 4 + 0] = p0 + p2 * t[NCLS_ + 0];
        g_boxes[row * 4 + 1] = p1 + p3 * t[NCLS_ + 1];
        g_boxes[row * 4 + 2] = p2 * expf(t[NCLS_ + 2]);
        g_boxes[row * 4 + 3] = p3 * expf(t[NCLS_ + 3]);
    }
}

// ---------------- k3: exact greedy NMS per batch ----------------
__global__ __launch_bounds__(512) void k3_nms(float* __restrict__ out) {
    __shared__ float sraw[512];
    __shared__ float ss[512], sx0[512], sy0[512], sx1[512], sy1[512], sa[512];
    __shared__ short sord[512];
    __shared__ unsigned char ssup[512];

    int b = blockIdx.x, t = threadIdx.x;
    int gi = b * 512 + t;
    float sc = g_score[gi];
    sraw[t] = sc;
    float bx = g_boxes[gi * 4 + 0], by = g_boxes[gi * 4 + 1];
    float bw = g_boxes[gi * 4 + 2], bh = g_boxes[gi * 4 + 3];
    __syncthreads();

    int r = 0;
    for (int i = 0; i < 512; i++) {
        float si = sraw[i];
        r += (si > sc) || (si == sc && i < t);
    }

    float x0 = fminf(fmaxf(bx, 0.f), 599.f);
    float y0 = fminf(fmaxf(by, 0.f), 599.f);
    float x1 = fminf(fmaxf(bx + bw - 1.f, 0.f), 599.f);
    float y1 = fminf(fmaxf(by + bh - 1.f, 0.f), 599.f);
    float area = fmaxf(x1 - x0 + 1.f, 0.f) * fmaxf(y1 - y0 + 1.f, 0.f);

    ss[r] = sc; sx0[r] = x0; sy0[r] = y0; sx1[r] = x1; sy1[r] = y1; sa[r] = area;
    sord[r] = (short)t;
    ssup[t] = 0;
    __syncthreads();

    for (int i = 0; i < 512; i++) {
        bool alive = (!ssup[i]) && (ss[i] > 0.f);
        if (alive && t != i) {
            float ix0 = fmaxf(sx0[i], sx0[t]);
            float iy0 = fmaxf(sy0[i], sy0[t]);
            float ix1 = fminf(sx1[i], sx1[t]);
            float iy1 = fminf(sy1[i], sy1[t]);
            float inter = fmaxf(ix1 - ix0 + 1.f, 0.f) * fmaxf(iy1 - iy0 + 1.f, 0.f);
            float iou = inter / (sa[i] + sa[t] - inter + 1e-9f);
            if (iou > 0.5f) ssup[t] = 1;
        }
        __syncthreads();
    }

    bool keep = (!ssup[t]) && (ss[t] > 0.f);
    int orig = sord[t];
    int go = b * 512 + orig;

    out[go] = keep ? ss[t] : 0.f;

    float obx = g_boxes[go * 4 + 0], oby = g_boxes[go * 4 + 1];
    float obw = g_boxes[go * 4 + 2], obh = g_boxes[go * 4 + 3];
    float* ob = out + NROI + (size_t)go * 4;
    if (keep) {
        ob[0] = obx; ob[1] = oby;
        ob[2] = obx + obw - 1.f;
        ob[3] = oby + obh - 1.f;
    } else {
        ob[0] = 0.f; ob[1] = 0.f; ob[2] = -1.f; ob[3] = -1.f;
    }
}

extern "C" void kernel_launch(void* const* d_in, const int* in_sizes, int n_in,
                              void* d_out, int out_size) {
    (void)in_sizes; (void)n_in; (void)out_size;
    const float* rois  = (const float*)d_in[0];
    const float* props = (const float*)d_in[1];
    const float* W1    = (const float*)d_in[2];
    const float* b1    = (const float*)d_in[3];
    const float* Wc    = (const float*)d_in[4];
    const float* bc    = (const float*)d_in[5];
    const float* Wr    = (const float*)d_in[6];
    const float* br    = (const float*)d_in[7];
    float* out = (float*)d_out;

    k_bias<<<NOUT, 256>>>(b1, Wc, bc, Wr, br);
    dim3 g1(KD / 512, HSPLIT);                 // (49, 8) = 392 blocks, one wave
    k1_partial<<<g1, 128>>>(W1, Wc, Wr);
    k_reduce<<<313600 / 256, 256>>>();
    dim3 g2(NRG, NSEG);                        // (32, 49)
    k2_main<<<g2, 128>>>(rois);
    k2r<<<NROI / 8, 256>>>(props);
    k3_nms<<<4, 512>>>(out);
}